// round 2
// baseline (speedup 1.0000x reference)
#include <cuda_runtime.h>
#include <cuda_bf16.h>

// Problem constants (shapes fixed by the dataset).
#define N_ROWS 4096
#define DIM    2048
#define HALF   2048
#define BM     128
#define BN     128
#define BK     16
#define NTILES (N_ROWS / BN)   // 32 column tiles
#define MTILES (HALF   / BM)   // 16 row tiles
#define MARGIN_F 0.3f

// Scratch (allocation-free rule: __device__ globals).
__device__ float g_sq[N_ROWS];
__device__ float g_ap[HALF * NTILES];
__device__ float g_an[HALF * NTILES];

// ---------------------------------------------------------------------------
// Kernel 1: sq[i] = sum_k A[i][k]^2 for all 4096 rows.
// ---------------------------------------------------------------------------
__global__ void sq_kernel(const float* __restrict__ A) {
    const int row = blockIdx.x;
    const float4* a = reinterpret_cast<const float4*>(A + (size_t)row * DIM);
    float s = 0.f;
    for (int i = threadIdx.x; i < DIM / 4; i += blockDim.x) {
        float4 v = a[i];
        s += v.x * v.x + v.y * v.y + v.z * v.z + v.w * v.w;
    }
    #pragma unroll
    for (int o = 16; o > 0; o >>= 1) s += __shfl_xor_sync(0xffffffffu, s, o);
    __shared__ float sm[8];
    if ((threadIdx.x & 31) == 0) sm[threadIdx.x >> 5] = s;
    __syncthreads();
    if (threadIdx.x == 0) {
        float t = 0.f;
        #pragma unroll
        for (int i = 0; i < 8; i++) t += sm[i];
        g_sq[row] = t;
    }
}

// ---------------------------------------------------------------------------
// Kernel 2: fused Gram-tile GEMM + dist + masked max/min per row-tile.
// Grid: (NTILES, MTILES). Block: 256 threads, each owns an 8x8 microtile.
// Writes per-row partial dist_ap / dist_an for its 128-column slab.
// ---------------------------------------------------------------------------
__global__ __launch_bounds__(256, 2)
void dist_kernel(const float* __restrict__ A, const int* __restrict__ targets) {
    __shared__ float As[BK][132];     // padded to dodge store conflicts
    __shared__ float Bs[BK][132];
    __shared__ float redAp[BM][16];
    __shared__ float redAn[BM][16];

    const int tid = threadIdx.x;
    const int tx  = tid & 15;         // column group
    const int ty  = tid >> 4;         // row group
    const int rowBase = blockIdx.y * BM;
    const int colBase = blockIdx.x * BN;

    float acc[8][8];
    #pragma unroll
    for (int i = 0; i < 8; i++)
        #pragma unroll
        for (int j = 0; j < 8; j++) acc[i][j] = 0.f;

    for (int kt = 0; kt < DIM; kt += BK) {
        // Load 128x16 A-tile (rows) and 128x16 B-tile (cols of the Gram matrix,
        // i.e. also rows of A). 512 float4 per tile -> 2 per thread, coalesced.
        #pragma unroll
        for (int s = 0; s < 2; s++) {
            const int idx = tid + s * 256;
            const int r  = idx >> 2;
            const int c4 = idx & 3;
            const float4 va = *reinterpret_cast<const float4*>(
                A + (size_t)(rowBase + r) * DIM + kt + c4 * 4);
            const float4 vb = *reinterpret_cast<const float4*>(
                A + (size_t)(colBase + r) * DIM + kt + c4 * 4);
            As[c4 * 4 + 0][r] = va.x; As[c4 * 4 + 1][r] = va.y;
            As[c4 * 4 + 2][r] = va.z; As[c4 * 4 + 3][r] = va.w;
            Bs[c4 * 4 + 0][r] = vb.x; Bs[c4 * 4 + 1][r] = vb.y;
            Bs[c4 * 4 + 2][r] = vb.z; Bs[c4 * 4 + 3][r] = vb.w;
        }
        __syncthreads();

        #pragma unroll
        for (int k = 0; k < BK; k++) {
            float ra[8], rb[8];
            *reinterpret_cast<float4*>(&ra[0]) =
                *reinterpret_cast<const float4*>(&As[k][ty * 8]);
            *reinterpret_cast<float4*>(&ra[4]) =
                *reinterpret_cast<const float4*>(&As[k][ty * 8 + 4]);
            *reinterpret_cast<float4*>(&rb[0]) =
                *reinterpret_cast<const float4*>(&Bs[k][tx * 8]);
            *reinterpret_cast<float4*>(&rb[4]) =
                *reinterpret_cast<const float4*>(&Bs[k][tx * 8 + 4]);
            #pragma unroll
            for (int i = 0; i < 8; i++)
                #pragma unroll
                for (int j = 0; j < 8; j++)
                    acc[i][j] = fmaf(ra[i], rb[j], acc[i][j]);
        }
        __syncthreads();
    }

    // Epilogue: dist + masked max/min, reduced across the 16 tx lanes per row.
    float sqc[8]; int tgc[8];
    #pragma unroll
    for (int j = 0; j < 8; j++) {
        const int c = colBase + tx * 8 + j;
        sqc[j] = g_sq[c];
        tgc[j] = targets[c];
    }
    #pragma unroll
    for (int i = 0; i < 8; i++) {
        const int r = rowBase + ty * 8 + i;
        const float sqr = g_sq[r];
        const int tgr = targets[r];
        float ap = -1e30f, an = 1e30f;
        #pragma unroll
        for (int j = 0; j < 8; j++) {
            const float d2 = sqr + sqc[j] - 2.0f * acc[i][j];
            const float d  = sqrtf(fmaxf(d2, 1e-12f));
            if (tgc[j] == tgr) ap = fmaxf(ap, d);
            else               an = fminf(an, d);
        }
        redAp[ty * 8 + i][tx] = ap;
        redAn[ty * 8 + i][tx] = an;
    }
    __syncthreads();

    if (tid < BM) {
        float ap = -1e30f, an = 1e30f;
        #pragma unroll
        for (int t = 0; t < 16; t++) {
            ap = fmaxf(ap, redAp[tid][t]);
            an = fminf(an, redAn[tid][t]);
        }
        g_ap[(size_t)(rowBase + tid) * NTILES + blockIdx.x] = ap;
        g_an[(size_t)(rowBase + tid) * NTILES + blockIdx.x] = an;
    }
}

// ---------------------------------------------------------------------------
// Kernel 3: deterministic single-block final reduction -> scalar loss.
// ---------------------------------------------------------------------------
__global__ void loss_kernel(float* __restrict__ out) {
    float s = 0.f;
    for (int r = threadIdx.x; r < HALF; r += blockDim.x) {
        float ap = -1e30f, an = 1e30f;
        #pragma unroll
        for (int t = 0; t < NTILES; t++) {
            ap = fmaxf(ap, g_ap[(size_t)r * NTILES + t]);
            an = fminf(an, g_an[(size_t)r * NTILES + t]);
        }
        s += fmaxf(ap - an + MARGIN_F, 0.f);
    }
    #pragma unroll
    for (int o = 16; o > 0; o >>= 1) s += __shfl_xor_sync(0xffffffffu, s, o);
    __shared__ float sm[8];
    if ((threadIdx.x & 31) == 0) sm[threadIdx.x >> 5] = s;
    __syncthreads();
    if (threadIdx.x == 0) {
        float t = 0.f;
        #pragma unroll
        for (int i = 0; i < 8; i++) t += sm[i];
        out[0] = t / (float)HALF;
    }
}

// ---------------------------------------------------------------------------
extern "C" void kernel_launch(void* const* d_in, const int* in_sizes, int n_in,
                              void* d_out, int out_size) {
    const float* A       = (const float*)d_in[0];   // [4096, 2048] fp32
    const int*   targets = (const int*)d_in[1];     // [4096] int32
    (void)in_sizes; (void)n_in; (void)out_size;     // batch_idx (d_in[2]) unused
    float* out = (float*)d_out;

    sq_kernel<<<N_ROWS, 256>>>(A);
    dim3 grid(NTILES, MTILES);
    dist_kernel<<<grid, 256>>>(A, targets);
    loss_kernel<<<1, 256>>>(out);
}

// round 4
// speedup vs baseline: 5.1293x; 5.1293x over previous
#include <cuda_runtime.h>
#include <cuda_bf16.h>
#include <cstdint>

// ---------------------------------------------------------------------------
// Problem constants
// ---------------------------------------------------------------------------
#define N_ROWS 4096
#define DIM    2048
#define HALF   2048
#define TILE_M 128
#define TILE_N 128
#define KC     64                 // bf16 elems per K chunk (128 B per row)
#define NKC    (DIM / KC)         // 32 chunks
#define NT_COL (N_ROWS / TILE_N)  // 32 column tiles
#define NT_ROW (HALF   / TILE_M)  // 16 row tiles
#define MARGIN_F 0.3f

// SMEM layout (dynamic)
#define STAGE_BYTES 32768         // A tile 16KB + B tile 16KB
#define STAGES 3
#define OFF_SQC 98304
#define OFF_TGC 98816
#define OFF_SQR 99328
#define OFF_TGR 99840
#define OFF_RAP 100352            // 128*4 floats
#define OFF_RAN 102400
#define SMEM_TOTAL 104448

// Scratch (__device__ globals; allocation-free rule)
__device__ __align__(16) __nv_bfloat16 g_Abf[(size_t)N_ROWS * DIM];  // 16 MB
__device__ float g_sq[N_ROWS];
__device__ float g_ap[HALF * NT_COL];
__device__ float g_an[HALF * NT_COL];

// ---------------------------------------------------------------------------
// PTX helpers (sm_80-era: cp.async + ldmatrix + mma.sync — legal on compute_100)
// ---------------------------------------------------------------------------
__device__ __forceinline__ uint32_t smem_u32(const void* p) {
    uint32_t a;
    asm("{ .reg .u64 t; cvta.to.shared.u64 t, %1; cvt.u32.u64 %0, t; }" : "=r"(a) : "l"(p));
    return a;
}
__device__ __forceinline__ void cp_async16(uint32_t saddr, const void* gaddr) {
    asm volatile("cp.async.cg.shared.global [%0], [%1], 16;" :: "r"(saddr), "l"(gaddr));
}
__device__ __forceinline__ void cp_commit() {
    asm volatile("cp.async.commit_group;");
}
__device__ __forceinline__ void cp_wait1() {
    asm volatile("cp.async.wait_group 1;");
}
__device__ __forceinline__ void ldmatrix_x4(uint32_t* r, uint32_t addr) {
    asm volatile("ldmatrix.sync.aligned.m8n8.x4.shared.b16 {%0,%1,%2,%3}, [%4];"
                 : "=r"(r[0]), "=r"(r[1]), "=r"(r[2]), "=r"(r[3]) : "r"(addr));
}
__device__ __forceinline__ void mma_bf16(float* c, const uint32_t* a, uint32_t b0, uint32_t b1) {
    asm volatile(
        "mma.sync.aligned.m16n8k16.row.col.f32.bf16.bf16.f32 "
        "{%0,%1,%2,%3}, {%4,%5,%6,%7}, {%8,%9}, {%0,%1,%2,%3};"
        : "+f"(c[0]), "+f"(c[1]), "+f"(c[2]), "+f"(c[3])
        : "r"(a[0]), "r"(a[1]), "r"(a[2]), "r"(a[3]), "r"(b0), "r"(b1));
}
// SW128 swizzle on a 128-byte row: 16B chunk index XOR (row & 7)
__device__ __forceinline__ uint32_t sw_off(uint32_t r, uint32_t c8) {
    return r * 128u + ((c8 ^ (r & 7u)) << 4);
}

// ---------------------------------------------------------------------------
// Kernel 1: fused fp32->bf16 convert + row sum-of-squares. One block per row.
// ---------------------------------------------------------------------------
__global__ void convert_sq_kernel(const float* __restrict__ A) {
    const int row = blockIdx.x;
    const float4* a4 = reinterpret_cast<const float4*>(A + (size_t)row * DIM);
    __nv_bfloat162* b2 = reinterpret_cast<__nv_bfloat162*>(g_Abf + (size_t)row * DIM);
    float s = 0.f;
    #pragma unroll
    for (int it = 0; it < 2; it++) {
        const int i = threadIdx.x + it * 256;   // 512 float4 per row
        float4 v = a4[i];
        s += v.x * v.x + v.y * v.y + v.z * v.z + v.w * v.w;
        b2[i * 2 + 0] = __floats2bfloat162_rn(v.x, v.y);
        b2[i * 2 + 1] = __floats2bfloat162_rn(v.z, v.w);
    }
    #pragma unroll
    for (int o = 16; o > 0; o >>= 1) s += __shfl_xor_sync(0xffffffffu, s, o);
    __shared__ float sm[8];
    if ((threadIdx.x & 31) == 0) sm[threadIdx.x >> 5] = s;
    __syncthreads();
    if (threadIdx.x == 0) {
        float t = 0.f;
        #pragma unroll
        for (int i = 0; i < 8; i++) t += sm[i];
        g_sq[row] = t;
    }
}

// ---------------------------------------------------------------------------
// Kernel 2: warp-MMA Gram tile (128x128) + fused dist/mask/max-min epilogue.
// Grid (NT_COL, NT_ROW), 256 threads = 8 warps in 2x4 (each warp 64x32).
// ---------------------------------------------------------------------------
__global__ __launch_bounds__(256, 2)
void dist_mma_kernel(const int* __restrict__ targets) {
    extern __shared__ __align__(128) char smem[];
    const uint32_t sb = smem_u32(smem);
    const int tid = threadIdx.x;
    const int lane = tid & 31;
    const int w = tid >> 5;
    const int rowBase = blockIdx.y * TILE_M;
    const int colBase = blockIdx.x * TILE_N;

    float* s_sqc = reinterpret_cast<float*>(smem + OFF_SQC);
    int*   s_tgc = reinterpret_cast<int*>(smem + OFF_TGC);
    float* s_sqr = reinterpret_cast<float*>(smem + OFF_SQR);
    int*   s_tgr = reinterpret_cast<int*>(smem + OFF_TGR);
    float* s_rap = reinterpret_cast<float*>(smem + OFF_RAP);
    float* s_ran = reinterpret_cast<float*>(smem + OFF_RAN);
    if (tid < TILE_N) {
        s_sqc[tid] = g_sq[colBase + tid];
        s_tgc[tid] = targets[colBase + tid];
        s_sqr[tid] = g_sq[rowBase + tid];
        s_tgr[tid] = targets[rowBase + tid];
    }

    // ---- stage loader: 2048 x 16B per stage (A tile 1024, B tile 1024) ----
    auto load_stage = [&](int s, int chunk) {
        const uint32_t stage = (uint32_t)s * STAGE_BYTES;
        #pragma unroll
        for (int i = 0; i < 8; ++i) {
            const int idx = tid + i * 256;
            const int li = idx & 1023;
            const int r = li >> 3;
            const int c8 = li & 7;
            const int grow = (idx < 1024 ? rowBase : colBase) + r;
            const void* g = g_Abf + (size_t)grow * DIM + chunk * KC + c8 * 8;
            const uint32_t soff = stage + (idx < 1024 ? 0u : 16384u) + sw_off(r, c8);
            cp_async16(sb + soff, g);
        }
        cp_commit();
    };

    load_stage(0, 0);
    load_stage(1, 1);

    float acc[4][4][4];
    #pragma unroll
    for (int i = 0; i < 4; i++)
        #pragma unroll
        for (int j = 0; j < 4; j++)
            #pragma unroll
            for (int e = 0; e < 4; e++) acc[i][j][e] = 0.f;

    const int mBase = (w >> 2) * 64;
    const int nBase = (w & 3) * 32;

    for (int c = 0; c < NKC; ++c) {
        cp_wait1();
        __syncthreads();
        if (c + 2 < NKC) load_stage((c + 2) % STAGES, c + 2);

        const uint32_t stA = sb + (uint32_t)(c % STAGES) * STAGE_BYTES;
        const uint32_t stB = stA + 16384u;
        #pragma unroll
        for (int ks = 0; ks < 4; ++ks) {           // 4 x k16 per 64-chunk
            uint32_t a[4][4];
            #pragma unroll
            for (int mi = 0; mi < 4; ++mi) {
                const uint32_t r = mBase + mi * 16 + (lane & 15);
                const uint32_t c8 = ks * 2 + (lane >> 4);
                ldmatrix_x4(a[mi], stA + sw_off(r, c8));
            }
            uint32_t b[2][4];
            #pragma unroll
            for (int nb = 0; nb < 2; ++nb) {
                const uint32_t r = nBase + nb * 16 + ((lane >> 4) << 3) + (lane & 7);
                const uint32_t c8 = ks * 2 + ((lane >> 3) & 1);
                ldmatrix_x4(b[nb], stB + sw_off(r, c8));
            }
            #pragma unroll
            for (int mi = 0; mi < 4; ++mi)
                #pragma unroll
                for (int nj = 0; nj < 4; ++nj)
                    mma_bf16(acc[mi][nj], a[mi], b[nj >> 1][(nj & 1) * 2],
                             b[nj >> 1][(nj & 1) * 2 + 1]);
        }
    }

    // ---- Epilogue: dist + masked max/min ----
    // Fragment layout (m16n8): thread holds (r=qrow, r+8) x (c=qcol*2, +1).
    const int qrow = lane >> 2;
    const int qcol = lane & 3;
    #pragma unroll
    for (int mi = 0; mi < 4; ++mi) {
        #pragma unroll
        for (int h = 0; h < 2; ++h) {
            const int rl = mBase + mi * 16 + qrow + h * 8;
            const float sqr = s_sqr[rl];
            const int tgr = s_tgr[rl];
            float ap = -1e30f, an = 1e30f;
            #pragma unroll
            for (int nj = 0; nj < 4; ++nj) {
                #pragma unroll
                for (int cc = 0; cc < 2; ++cc) {
                    const int cl = nBase + nj * 8 + qcol * 2 + cc;
                    const float d2 = sqr + s_sqc[cl] - 2.0f * acc[mi][nj][h * 2 + cc];
                    const float d = sqrtf(fmaxf(d2, 1e-12f));
                    if (s_tgc[cl] == tgr) ap = fmaxf(ap, d);
                    else                  an = fminf(an, d);
                }
            }
            // reduce over the 4 quad-lanes sharing this row
            ap = fmaxf(ap, __shfl_xor_sync(0xffffffffu, ap, 1));
            ap = fmaxf(ap, __shfl_xor_sync(0xffffffffu, ap, 2));
            an = fminf(an, __shfl_xor_sync(0xffffffffu, an, 1));
            an = fminf(an, __shfl_xor_sync(0xffffffffu, an, 2));
            if (qcol == 0) {
                s_rap[rl * 4 + (w & 3)] = ap;
                s_ran[rl * 4 + (w & 3)] = an;
            }
        }
    }
    __syncthreads();
    if (tid < TILE_M) {
        float ap = -1e30f, an = 1e30f;
        #pragma unroll
        for (int t = 0; t < 4; ++t) {
            ap = fmaxf(ap, s_rap[tid * 4 + t]);
            an = fminf(an, s_ran[tid * 4 + t]);
        }
        g_ap[(size_t)(rowBase + tid) * NT_COL + blockIdx.x] = ap;
        g_an[(size_t)(rowBase + tid) * NT_COL + blockIdx.x] = an;
    }
}

// ---------------------------------------------------------------------------
// Kernel 3: deterministic final reduction -> scalar loss.
// ---------------------------------------------------------------------------
__global__ void loss_kernel(float* __restrict__ out) {
    float s = 0.f;
    for (int r = threadIdx.x; r < HALF; r += blockDim.x) {
        float ap = -1e30f, an = 1e30f;
        #pragma unroll
        for (int t = 0; t < NT_COL; t++) {
            ap = fmaxf(ap, g_ap[(size_t)r * NT_COL + t]);
            an = fminf(an, g_an[(size_t)r * NT_COL + t]);
        }
        s += fmaxf(ap - an + MARGIN_F, 0.f);
    }
    #pragma unroll
    for (int o = 16; o > 0; o >>= 1) s += __shfl_xor_sync(0xffffffffu, s, o);
    __shared__ float sm[8];
    if ((threadIdx.x & 31) == 0) sm[threadIdx.x >> 5] = s;
    __syncthreads();
    if (threadIdx.x == 0) {
        float t = 0.f;
        #pragma unroll
        for (int i = 0; i < 8; i++) t += sm[i];
        out[0] = t / (float)HALF;
    }
}

// ---------------------------------------------------------------------------
extern "C" void kernel_launch(void* const* d_in, const int* in_sizes, int n_in,
                              void* d_out, int out_size) {
    const float* A       = (const float*)d_in[0];   // [4096, 2048] fp32
    const int*   targets = (const int*)d_in[1];     // [4096] int32
    (void)in_sizes; (void)n_in; (void)out_size;
    float* out = (float*)d_out;

    cudaFuncSetAttribute(dist_mma_kernel,
                         cudaFuncAttributeMaxDynamicSharedMemorySize, SMEM_TOTAL);

    convert_sq_kernel<<<N_ROWS, 256>>>(A);
    dim3 grid(NT_COL, NT_ROW);
    dist_mma_kernel<<<grid, 256, SMEM_TOTAL>>>(targets);
    loss_kernel<<<1, 256>>>(out);
}

// round 5
// speedup vs baseline: 6.9367x; 1.3524x over previous
#include <cuda_runtime.h>
#include <cuda_bf16.h>
#include <cstdint>

// ---------------------------------------------------------------------------
// Problem constants
// ---------------------------------------------------------------------------
#define N_ROWS 4096
#define DIM    2048
#define HALF   2048
#define TILE_M 128
#define TILE_N 128
#define KC     128                // int8 elems per K chunk (128 B per row)
#define NKC    (DIM / KC)         // 16 chunks
#define NT_COL (N_ROWS / TILE_N)  // 32 column tiles
#define NT_ROW (HALF   / TILE_M)  // 16 row tiles
#define MARGIN_F 0.3f

// SMEM layout (dynamic)
#define STAGE_BYTES 32768         // A tile 16KB + B tile 16KB
#define STAGES 3
#define OFF_SQC 98304
#define OFF_TGC 98816
#define OFF_SQR 99328
#define OFF_TGR 99840
#define OFF_SCR 100352            // row quant scales
#define OFF_SCC 100864            // col quant scales
#define OFF_RAP 101376            // 128*4 floats
#define OFF_RAN 103424
#define SMEM_TOTAL 105472

// Scratch (__device__ globals; allocation-free rule)
__device__ __align__(16) int8_t g_Aq[(size_t)N_ROWS * DIM];   // 8 MB
__device__ float g_sq[N_ROWS];
__device__ float g_scale[N_ROWS];
__device__ float g_ap[HALF * NT_COL];
__device__ float g_an[HALF * NT_COL];

// ---------------------------------------------------------------------------
// PTX helpers (sm_80-era: cp.async + ldmatrix + mma.sync — legal on compute_100)
// ---------------------------------------------------------------------------
__device__ __forceinline__ uint32_t smem_u32(const void* p) {
    uint32_t a;
    asm("{ .reg .u64 t; cvta.to.shared.u64 t, %1; cvt.u32.u64 %0, t; }" : "=r"(a) : "l"(p));
    return a;
}
__device__ __forceinline__ void cp_async16(uint32_t saddr, const void* gaddr) {
    asm volatile("cp.async.cg.shared.global [%0], [%1], 16;" :: "r"(saddr), "l"(gaddr));
}
__device__ __forceinline__ void cp_commit() {
    asm volatile("cp.async.commit_group;");
}
__device__ __forceinline__ void cp_wait1() {
    asm volatile("cp.async.wait_group 1;");
}
__device__ __forceinline__ void ldmatrix_x4(uint32_t* r, uint32_t addr) {
    asm volatile("ldmatrix.sync.aligned.m8n8.x4.shared.b16 {%0,%1,%2,%3}, [%4];"
                 : "=r"(r[0]), "=r"(r[1]), "=r"(r[2]), "=r"(r[3]) : "r"(addr));
}
// int8 MMA: byte-level fragment layout identical to bf16 m16n8k16 (b16 == 2 x s8)
__device__ __forceinline__ void mma_s8(int* c, const uint32_t* a, uint32_t b0, uint32_t b1) {
    asm volatile(
        "mma.sync.aligned.m16n8k32.row.col.s32.s8.s8.s32 "
        "{%0,%1,%2,%3}, {%4,%5,%6,%7}, {%8,%9}, {%0,%1,%2,%3};"
        : "+r"(c[0]), "+r"(c[1]), "+r"(c[2]), "+r"(c[3])
        : "r"(a[0]), "r"(a[1]), "r"(a[2]), "r"(a[3]), "r"(b0), "r"(b1));
}
// SW128 swizzle on a 128-byte row: 16B chunk index XOR (row & 7)
__device__ __forceinline__ uint32_t sw_off(uint32_t r, uint32_t c8) {
    return r * 128u + ((c8 ^ (r & 7u)) << 4);
}

// ---------------------------------------------------------------------------
// Kernel 1: per-row absmax quantize fp32 -> int8 + row sum-of-squares (fp32).
// One block (256 thr) per row; row lives in registers between passes.
// ---------------------------------------------------------------------------
__global__ void quant_sq_kernel(const float* __restrict__ A) {
    const int row = blockIdx.x;
    const float4* a4 = reinterpret_cast<const float4*>(A + (size_t)row * DIM);
    float4 v0 = a4[threadIdx.x];
    float4 v1 = a4[threadIdx.x + 256];

    float s = v0.x * v0.x + v0.y * v0.y + v0.z * v0.z + v0.w * v0.w
            + v1.x * v1.x + v1.y * v1.y + v1.z * v1.z + v1.w * v1.w;
    float m = fmaxf(fmaxf(fmaxf(fabsf(v0.x), fabsf(v0.y)), fmaxf(fabsf(v0.z), fabsf(v0.w))),
                    fmaxf(fmaxf(fabsf(v1.x), fabsf(v1.y)), fmaxf(fabsf(v1.z), fabsf(v1.w))));
    #pragma unroll
    for (int o = 16; o > 0; o >>= 1) {
        s += __shfl_xor_sync(0xffffffffu, s, o);
        m = fmaxf(m, __shfl_xor_sync(0xffffffffu, m, o));
    }
    __shared__ float sm_s[8], sm_m[8];
    if ((threadIdx.x & 31) == 0) { sm_s[threadIdx.x >> 5] = s; sm_m[threadIdx.x >> 5] = m; }
    __syncthreads();
    float ts = 0.f, tm = 0.f;
    #pragma unroll
    for (int i = 0; i < 8; i++) { ts += sm_s[i]; tm = fmaxf(tm, sm_m[i]); }
    if (threadIdx.x == 0) {
        g_sq[row] = ts;
        g_scale[row] = fmaxf(tm, 1e-30f) / 127.0f;
    }
    const float inv = 127.0f / fmaxf(tm, 1e-30f);

    uint32_t* q32 = reinterpret_cast<uint32_t*>(g_Aq + (size_t)row * DIM);
    auto pack = [inv](float4 v) -> uint32_t {
        int q0 = __float2int_rn(v.x * inv), q1 = __float2int_rn(v.y * inv);
        int q2 = __float2int_rn(v.z * inv), q3 = __float2int_rn(v.w * inv);
        return (uint32_t)(uint8_t)(int8_t)q0 | ((uint32_t)(uint8_t)(int8_t)q1 << 8) |
               ((uint32_t)(uint8_t)(int8_t)q2 << 16) | ((uint32_t)(uint8_t)(int8_t)q3 << 24);
    };
    q32[threadIdx.x]       = pack(v0);
    q32[threadIdx.x + 256] = pack(v1);
}

// ---------------------------------------------------------------------------
// Kernel 2: int8 warp-MMA Gram tile (128x128) + fused dist/mask/max-min.
// Grid (NT_COL, NT_ROW), 256 threads = 8 warps in 2x4 (each warp 64x32).
// ---------------------------------------------------------------------------
__global__ __launch_bounds__(256, 2)
void dist_imma_kernel(const int* __restrict__ targets) {
    extern __shared__ __align__(128) char smem[];
    const uint32_t sb = smem_u32(smem);
    const int tid = threadIdx.x;
    const int lane = tid & 31;
    const int w = tid >> 5;
    const int rowBase = blockIdx.y * TILE_M;
    const int colBase = blockIdx.x * TILE_N;

    float* s_sqc = reinterpret_cast<float*>(smem + OFF_SQC);
    int*   s_tgc = reinterpret_cast<int*>(smem + OFF_TGC);
    float* s_sqr = reinterpret_cast<float*>(smem + OFF_SQR);
    int*   s_tgr = reinterpret_cast<int*>(smem + OFF_TGR);
    float* s_scr = reinterpret_cast<float*>(smem + OFF_SCR);
    float* s_scc = reinterpret_cast<float*>(smem + OFF_SCC);
    float* s_rap = reinterpret_cast<float*>(smem + OFF_RAP);
    float* s_ran = reinterpret_cast<float*>(smem + OFF_RAN);
    if (tid < TILE_N) {
        s_sqc[tid] = g_sq[colBase + tid];
        s_tgc[tid] = targets[colBase + tid];
        s_scc[tid] = g_scale[colBase + tid];
        s_sqr[tid] = g_sq[rowBase + tid];
        s_tgr[tid] = targets[rowBase + tid];
        s_scr[tid] = g_scale[rowBase + tid];
    }

    // ---- stage loader: 2048 x 16B per stage (A tile 1024, B tile 1024) ----
    auto load_stage = [&](int s, int chunk) {
        const uint32_t stage = (uint32_t)s * STAGE_BYTES;
        #pragma unroll
        for (int i = 0; i < 8; ++i) {
            const int idx = tid + i * 256;
            const int li = idx & 1023;
            const int r = li >> 3;
            const int c8 = li & 7;
            const int grow = (idx < 1024 ? rowBase : colBase) + r;
            const void* g = g_Aq + (size_t)grow * DIM + chunk * KC + c8 * 16;
            const uint32_t soff = stage + (idx < 1024 ? 0u : 16384u) + sw_off(r, c8);
            cp_async16(sb + soff, g);
        }
        cp_commit();
    };

    load_stage(0, 0);
    load_stage(1, 1);

    int acc[4][4][4];
    #pragma unroll
    for (int i = 0; i < 4; i++)
        #pragma unroll
        for (int j = 0; j < 4; j++)
            #pragma unroll
            for (int e = 0; e < 4; e++) acc[i][j][e] = 0;

    const int mBase = (w >> 2) * 64;
    const int nBase = (w & 3) * 32;

    for (int c = 0; c < NKC; ++c) {
        cp_wait1();
        __syncthreads();
        if (c + 2 < NKC) load_stage((c + 2) % STAGES, c + 2);

        const uint32_t stA = sb + (uint32_t)(c % STAGES) * STAGE_BYTES;
        const uint32_t stB = stA + 16384u;
        #pragma unroll
        for (int ks = 0; ks < 4; ++ks) {           // 4 x k32(int8) per 128-chunk
            uint32_t a[4][4];
            #pragma unroll
            for (int mi = 0; mi < 4; ++mi) {
                const uint32_t r = mBase + mi * 16 + (lane & 15);
                const uint32_t c8 = ks * 2 + (lane >> 4);
                ldmatrix_x4(a[mi], stA + sw_off(r, c8));
            }
            uint32_t b[2][4];
            #pragma unroll
            for (int nb = 0; nb < 2; ++nb) {
                const uint32_t r = nBase + nb * 16 + ((lane >> 4) << 3) + (lane & 7);
                const uint32_t c8 = ks * 2 + ((lane >> 3) & 1);
                ldmatrix_x4(b[nb], stB + sw_off(r, c8));
            }
            #pragma unroll
            for (int mi = 0; mi < 4; ++mi)
                #pragma unroll
                for (int nj = 0; nj < 4; ++nj)
                    mma_s8(acc[mi][nj], a[mi], b[nj >> 1][(nj & 1) * 2],
                           b[nj >> 1][(nj & 1) * 2 + 1]);
        }
    }

    // ---- Epilogue: dist + masked max/min ----
    // Fragment layout (m16n8): thread holds (r=qrow, r+8) x (c=qcol*2, +1).
    const int qrow = lane >> 2;
    const int qcol = lane & 3;
    #pragma unroll
    for (int mi = 0; mi < 4; ++mi) {
        #pragma unroll
        for (int h = 0; h < 2; ++h) {
            const int rl = mBase + mi * 16 + qrow + h * 8;
            const float sqr = s_sqr[rl];
            const float sr2 = 2.0f * s_scr[rl];
            const int tgr = s_tgr[rl];
            float ap = -1e30f, an = 1e30f;
            #pragma unroll
            for (int nj = 0; nj < 4; ++nj) {
                #pragma unroll
                for (int cc = 0; cc < 2; ++cc) {
                    const int cl = nBase + nj * 8 + qcol * 2 + cc;
                    const float dot = sr2 * s_scc[cl] * (float)acc[mi][nj][h * 2 + cc];
                    const float d2 = sqr + s_sqc[cl] - dot;
                    const float d = sqrtf(fmaxf(d2, 1e-12f));
                    if (s_tgc[cl] == tgr) ap = fmaxf(ap, d);
                    else                  an = fminf(an, d);
                }
            }
            ap = fmaxf(ap, __shfl_xor_sync(0xffffffffu, ap, 1));
            ap = fmaxf(ap, __shfl_xor_sync(0xffffffffu, ap, 2));
            an = fminf(an, __shfl_xor_sync(0xffffffffu, an, 1));
            an = fminf(an, __shfl_xor_sync(0xffffffffu, an, 2));
            if (qcol == 0) {
                s_rap[rl * 4 + (w & 3)] = ap;
                s_ran[rl * 4 + (w & 3)] = an;
            }
        }
    }
    __syncthreads();
    if (tid < TILE_M) {
        float ap = -1e30f, an = 1e30f;
        #pragma unroll
        for (int t = 0; t < 4; ++t) {
            ap = fmaxf(ap, s_rap[tid * 4 + t]);
            an = fminf(an, s_ran[tid * 4 + t]);
        }
        g_ap[(size_t)(rowBase + tid) * NT_COL + blockIdx.x] = ap;
        g_an[(size_t)(rowBase + tid) * NT_COL + blockIdx.x] = an;
    }
}

// ---------------------------------------------------------------------------
// Kernel 3: deterministic final reduction -> scalar loss.
// ---------------------------------------------------------------------------
__global__ void loss_kernel(float* __restrict__ out) {
    float s = 0.f;
    for (int r = threadIdx.x; r < HALF; r += blockDim.x) {
        float ap = -1e30f, an = 1e30f;
        #pragma unroll
        for (int t = 0; t < NT_COL; t++) {
            ap = fmaxf(ap, g_ap[(size_t)r * NT_COL + t]);
            an = fminf(an, g_an[(size_t)r * NT_COL + t]);
        }
        s += fmaxf(ap - an + MARGIN_F, 0.f);
    }
    #pragma unroll
    for (int o = 16; o > 0; o >>= 1) s += __shfl_xor_sync(0xffffffffu, s, o);
    __shared__ float sm[8];
    if ((threadIdx.x & 31) == 0) sm[threadIdx.x >> 5] = s;
    __syncthreads();
    if (threadIdx.x == 0) {
        float t = 0.f;
        #pragma unroll
        for (int i = 0; i < 8; i++) t += sm[i];
        out[0] = t / (float)HALF;
    }
}

// ---------------------------------------------------------------------------
extern "C" void kernel_launch(void* const* d_in, const int* in_sizes, int n_in,
                              void* d_out, int out_size) {
    const float* A       = (const float*)d_in[0];   // [4096, 2048] fp32
    const int*   targets = (const int*)d_in[1];     // [4096] int32
    (void)in_sizes; (void)n_in; (void)out_size;
    float* out = (float*)d_out;

    cudaFuncSetAttribute(dist_imma_kernel,
                         cudaFuncAttributeMaxDynamicSharedMemorySize, SMEM_TOTAL);

    quant_sq_kernel<<<N_ROWS, 256>>>(A);
    dim3 grid(NT_COL, NT_ROW);
    dist_imma_kernel<<<grid, 256, SMEM_TOTAL>>>(targets);
    loss_kernel<<<1, 256>>>(out);
}

// round 6
// speedup vs baseline: 7.1506x; 1.0308x over previous
#include <cuda_runtime.h>
#include <cuda_bf16.h>
#include <cstdint>

// ---------------------------------------------------------------------------
// Problem constants
// ---------------------------------------------------------------------------
#define N_ROWS 4096
#define DIM    2048
#define HALF   2048
#define TILE_M 128
#define TILE_N 128
#define KC     128                // int8 elems per K chunk (128 B per row)
#define NKC    (DIM / KC)         // 16 chunks
#define NT_COL (N_ROWS / TILE_N)  // 32 column tiles
#define NT_ROW (HALF   / TILE_M)  // 16 row tiles
#define MARGIN_F 0.3f
#define SLAB_BYTES ((size_t)N_ROWS * 128)   // bytes per K-chunk slab in g_Aq

// SMEM layout (dynamic)
#define STAGE_BYTES 32768         // A tile 16KB + B tile 16KB
#define STAGES 3
#define OFF_MBAR 98304            // 3 x 8B mbarriers
#define OFF_SQC  98432
#define OFF_TGC  98944
#define OFF_SQR  99456
#define OFF_TGR  99968
#define OFF_SCR  100480           // row quant scales
#define OFF_SCC  100992           // col quant scales
#define OFF_RAP  101504           // 128*4 floats
#define OFF_RAN  103552
#define SMEM_TOTAL 105600

// Scratch (__device__ globals; allocation-free rule)
// Layout: [chunk][row][128B], SW128 swizzle pre-applied within each 8-row block,
// so a 128-row tile slab is 16KB contiguous and bulk-copies directly into the
// ldmatrix-ready smem image.
__device__ __align__(128) int8_t g_Aq[(size_t)N_ROWS * DIM];   // 8 MB
__device__ float g_sq[N_ROWS];
__device__ float g_scale[N_ROWS];
__device__ float g_ap[HALF * NT_COL];
__device__ float g_an[HALF * NT_COL];

// ---------------------------------------------------------------------------
// PTX helpers (sm_80/sm_90 baseline: ldmatrix, mma.sync, cp.async.bulk, mbarrier)
// ---------------------------------------------------------------------------
__device__ __forceinline__ uint32_t smem_u32(const void* p) {
    uint32_t a;
    asm("{ .reg .u64 t; cvta.to.shared.u64 t, %1; cvt.u32.u64 %0, t; }" : "=r"(a) : "l"(p));
    return a;
}
__device__ __forceinline__ void mbar_init(uint32_t a, uint32_t cnt) {
    asm volatile("mbarrier.init.shared.b64 [%0], %1;" :: "r"(a), "r"(cnt) : "memory");
}
__device__ __forceinline__ void mbar_expect_tx(uint32_t a, uint32_t bytes) {
    asm volatile("mbarrier.arrive.expect_tx.shared.b64 _, [%0], %1;"
                 :: "r"(a), "r"(bytes) : "memory");
}
__device__ __forceinline__ void mbar_wait(uint32_t a, uint32_t parity) {
    asm volatile(
        "{\n\t.reg .pred P;\n"
        "W_%=:\n\t"
        "mbarrier.try_wait.parity.shared.b64 P, [%0], %1, 0x989680;\n\t"
        "@P bra.uni D_%=;\n\t"
        "bra.uni W_%=;\n"
        "D_%=:\n\t}"
        :: "r"(a), "r"(parity) : "memory");
}
__device__ __forceinline__ void bulk_g2s(uint32_t sdst, const void* gsrc,
                                         uint32_t bytes, uint32_t mbar) {
    asm volatile(
        "cp.async.bulk.shared::cta.global.mbarrier::complete_tx::bytes [%0], [%1], %2, [%3];"
        :: "r"(sdst), "l"(gsrc), "r"(bytes), "r"(mbar) : "memory");
}
__device__ __forceinline__ void ldmatrix_x4(uint32_t* r, uint32_t addr) {
    asm volatile("ldmatrix.sync.aligned.m8n8.x4.shared.b16 {%0,%1,%2,%3}, [%4];"
                 : "=r"(r[0]), "=r"(r[1]), "=r"(r[2]), "=r"(r[3]) : "r"(addr));
}
// int8 MMA: byte-level fragment layout identical to bf16 m16n8k16 (b16 == 2 x s8)
__device__ __forceinline__ void mma_s8(int* c, const uint32_t* a, uint32_t b0, uint32_t b1) {
    asm volatile(
        "mma.sync.aligned.m16n8k32.row.col.s32.s8.s8.s32 "
        "{%0,%1,%2,%3}, {%4,%5,%6,%7}, {%8,%9}, {%0,%1,%2,%3};"
        : "+r"(c[0]), "+r"(c[1]), "+r"(c[2]), "+r"(c[3])
        : "r"(a[0]), "r"(a[1]), "r"(a[2]), "r"(a[3]), "r"(b0), "r"(b1));
}
// SW128 swizzle on a 128-byte row: 16B chunk index XOR (row & 7)
__device__ __forceinline__ uint32_t sw_off(uint32_t r, uint32_t c8) {
    return r * 128u + ((c8 ^ (r & 7u)) << 4);
}

// ---------------------------------------------------------------------------
// Kernel 1: per-row absmax quantize fp32 -> int8 (pre-swizzled chunk-blocked
// layout) + row sum-of-squares (fp32). One block (256 thr) per row.
// ---------------------------------------------------------------------------
__global__ void quant_sq_kernel(const float* __restrict__ A) {
    const int row = blockIdx.x;
    const float4* a4 = reinterpret_cast<const float4*>(A + (size_t)row * DIM);
    float4 v0 = a4[threadIdx.x];
    float4 v1 = a4[threadIdx.x + 256];

    float s = v0.x * v0.x + v0.y * v0.y + v0.z * v0.z + v0.w * v0.w
            + v1.x * v1.x + v1.y * v1.y + v1.z * v1.z + v1.w * v1.w;
    float m = fmaxf(fmaxf(fmaxf(fabsf(v0.x), fabsf(v0.y)), fmaxf(fabsf(v0.z), fabsf(v0.w))),
                    fmaxf(fmaxf(fabsf(v1.x), fabsf(v1.y)), fmaxf(fabsf(v1.z), fabsf(v1.w))));
    #pragma unroll
    for (int o = 16; o > 0; o >>= 1) {
        s += __shfl_xor_sync(0xffffffffu, s, o);
        m = fmaxf(m, __shfl_xor_sync(0xffffffffu, m, o));
    }
    __shared__ float sm_s[8], sm_m[8];
    if ((threadIdx.x & 31) == 0) { sm_s[threadIdx.x >> 5] = s; sm_m[threadIdx.x >> 5] = m; }
    __syncthreads();
    float ts = 0.f, tm = 0.f;
    #pragma unroll
    for (int i = 0; i < 8; i++) { ts += sm_s[i]; tm = fmaxf(tm, sm_m[i]); }
    if (threadIdx.x == 0) {
        g_sq[row] = ts;
        g_scale[row] = fmaxf(tm, 1e-30f) / 127.0f;
    }
    const float inv = 127.0f / fmaxf(tm, 1e-30f);

    uint32_t* q32 = reinterpret_cast<uint32_t*>(g_Aq);
    auto pack = [inv](float4 v) -> uint32_t {
        int q0 = __float2int_rn(v.x * inv), q1 = __float2int_rn(v.y * inv);
        int q2 = __float2int_rn(v.z * inv), q3 = __float2int_rn(v.w * inv);
        return (uint32_t)(uint8_t)(int8_t)q0 | ((uint32_t)(uint8_t)(int8_t)q1 << 8) |
               ((uint32_t)(uint8_t)(int8_t)q2 << 16) | ((uint32_t)(uint8_t)(int8_t)q3 << 24);
    };
    // j32 = 4-byte column index in [0, 512). chunk = j32>>5; c8 = (j32>>2)&7.
    auto qidx = [row](int j32) -> size_t {
        const int c  = j32 >> 5;
        const int c8 = (j32 >> 2) & 7;
        const int w  = j32 & 3;
        const size_t byteoff = (size_t)c * SLAB_BYTES + (size_t)row * 128 +
                               (size_t)(((uint32_t)c8 ^ ((uint32_t)row & 7u)) << 4) + w * 4;
        return byteoff >> 2;
    };
    q32[qidx(threadIdx.x)]       = pack(v0);
    q32[qidx(threadIdx.x + 256)] = pack(v1);
}

// ---------------------------------------------------------------------------
// Kernel 2: int8 warp-MMA Gram tile (128x128) + fused dist/mask/max-min.
// Loads via cp.async.bulk (2 x 16KB contiguous slabs per chunk, thread 0 only).
// Grid (NT_COL, NT_ROW), 256 threads = 8 warps in 2x4 (each warp 64x32).
// ---------------------------------------------------------------------------
__global__ __launch_bounds__(256, 2)
void dist_imma_kernel(const int* __restrict__ targets) {
    extern __shared__ __align__(128) char smem[];
    const uint32_t sb = smem_u32(smem);
    const int tid = threadIdx.x;
    const int lane = tid & 31;
    const int w = tid >> 5;
    const int rowBase = blockIdx.y * TILE_M;
    const int colBase = blockIdx.x * TILE_N;

    float* s_sqc = reinterpret_cast<float*>(smem + OFF_SQC);
    int*   s_tgc = reinterpret_cast<int*>(smem + OFF_TGC);
    float* s_sqr = reinterpret_cast<float*>(smem + OFF_SQR);
    int*   s_tgr = reinterpret_cast<int*>(smem + OFF_TGR);
    float* s_scr = reinterpret_cast<float*>(smem + OFF_SCR);
    float* s_scc = reinterpret_cast<float*>(smem + OFF_SCC);
    float* s_rap = reinterpret_cast<float*>(smem + OFF_RAP);
    float* s_ran = reinterpret_cast<float*>(smem + OFF_RAN);

    if (tid == 0) {
        #pragma unroll
        for (int s = 0; s < STAGES; ++s) mbar_init(sb + OFF_MBAR + s * 8, 1);
    }
    if (tid < TILE_N) {
        s_sqc[tid] = g_sq[colBase + tid];
        s_tgc[tid] = targets[colBase + tid];
        s_scc[tid] = g_scale[colBase + tid];
        s_sqr[tid] = g_sq[rowBase + tid];
        s_tgr[tid] = targets[rowBase + tid];
        s_scr[tid] = g_scale[rowBase + tid];
    }
    __syncthreads();

    auto issue_chunk = [&](int s, int chunk) {
        const uint32_t mbar = sb + OFF_MBAR + s * 8;
        const uint32_t st = sb + (uint32_t)s * STAGE_BYTES;
        mbar_expect_tx(mbar, STAGE_BYTES);
        bulk_g2s(st, g_Aq + (size_t)chunk * SLAB_BYTES + (size_t)rowBase * 128,
                 16384u, mbar);
        bulk_g2s(st + 16384u, g_Aq + (size_t)chunk * SLAB_BYTES + (size_t)colBase * 128,
                 16384u, mbar);
    };
    if (tid == 0) {
        issue_chunk(0, 0);
        issue_chunk(1, 1);
        issue_chunk(2, 2);
    }

    int acc[4][4][4];
    #pragma unroll
    for (int i = 0; i < 4; i++)
        #pragma unroll
        for (int j = 0; j < 4; j++)
            #pragma unroll
            for (int e = 0; e < 4; e++) acc[i][j][e] = 0;

    const int mBase = (w >> 2) * 64;
    const int nBase = (w & 3) * 32;
    uint32_t ph0 = 0, ph1 = 0, ph2 = 0;

    for (int c = 0; c < NKC; ++c) {
        const int s = c % STAGES;
        uint32_t& ph = (s == 0) ? ph0 : (s == 1) ? ph1 : ph2;
        mbar_wait(sb + OFF_MBAR + s * 8, ph & 1);
        ph++;

        const uint32_t stA = sb + (uint32_t)s * STAGE_BYTES;
        const uint32_t stB = stA + 16384u;
        #pragma unroll
        for (int ks = 0; ks < 4; ++ks) {           // 4 x k32(int8) per 128-chunk
            uint32_t a[4][4];
            #pragma unroll
            for (int mi = 0; mi < 4; ++mi) {
                const uint32_t r = mBase + mi * 16 + (lane & 15);
                const uint32_t c8 = ks * 2 + (lane >> 4);
                ldmatrix_x4(a[mi], stA + sw_off(r, c8));
            }
            uint32_t b[2][4];
            #pragma unroll
            for (int nb = 0; nb < 2; ++nb) {
                const uint32_t r = nBase + nb * 16 + ((lane >> 4) << 3) + (lane & 7);
                const uint32_t c8 = ks * 2 + ((lane >> 3) & 1);
                ldmatrix_x4(b[nb], stB + sw_off(r, c8));
            }
            #pragma unroll
            for (int mi = 0; mi < 4; ++mi)
                #pragma unroll
                for (int nj = 0; nj < 4; ++nj)
                    mma_s8(acc[mi][nj], a[mi], b[nj >> 1][(nj & 1) * 2],
                           b[nj >> 1][(nj & 1) * 2 + 1]);
        }
        __syncthreads();               // all warps done with stage s
        if (tid == 0 && c + STAGES < NKC) issue_chunk(s, c + STAGES);
    }

    // ---- Epilogue: dist + masked max/min ----
    // Fragment layout (m16n8): thread holds (r=qrow, r+8) x (c=qcol*2, +1).
    const int qrow = lane >> 2;
    const int qcol = lane & 3;
    #pragma unroll
    for (int mi = 0; mi < 4; ++mi) {
        #pragma unroll
        for (int h = 0; h < 2; ++h) {
            const int rl = mBase + mi * 16 + qrow + h * 8;
            const float sqr = s_sqr[rl];
            const float sr2 = 2.0f * s_scr[rl];
            const int tgr = s_tgr[rl];
            float ap = -1e30f, an = 1e30f;
            #pragma unroll
            for (int nj = 0; nj < 4; ++nj) {
                #pragma unroll
                for (int cc = 0; cc < 2; ++cc) {
                    const int cl = nBase + nj * 8 + qcol * 2 + cc;
                    const float dot = sr2 * s_scc[cl] * (float)acc[mi][nj][h * 2 + cc];
                    const float d2 = sqr + s_sqc[cl] - dot;
                    const float d = sqrtf(fmaxf(d2, 1e-12f));
                    if (s_tgc[cl] == tgr) ap = fmaxf(ap, d);
                    else                  an = fminf(an, d);
                }
            }
            ap = fmaxf(ap, __shfl_xor_sync(0xffffffffu, ap, 1));
            ap = fmaxf(ap, __shfl_xor_sync(0xffffffffu, ap, 2));
            an = fminf(an, __shfl_xor_sync(0xffffffffu, an, 1));
            an = fminf(an, __shfl_xor_sync(0xffffffffu, an, 2));
            if (qcol == 0) {
                s_rap[rl * 4 + (w & 3)] = ap;
                s_ran[rl * 4 + (w & 3)] = an;
            }
        }
    }
    __syncthreads();
    if (tid < TILE_M) {
        float ap = -1e30f, an = 1e30f;
        #pragma unroll
        for (int t = 0; t < 4; ++t) {
            ap = fmaxf(ap, s_rap[tid * 4 + t]);
            an = fminf(an, s_ran[tid * 4 + t]);
        }
        g_ap[(size_t)(rowBase + tid) * NT_COL + blockIdx.x] = ap;
        g_an[(size_t)(rowBase + tid) * NT_COL + blockIdx.x] = an;
    }
}

// ---------------------------------------------------------------------------
// Kernel 3: deterministic final reduction -> scalar loss.
// ---------------------------------------------------------------------------
__global__ void loss_kernel(float* __restrict__ out) {
    float s = 0.f;
    for (int r = threadIdx.x; r < HALF; r += blockDim.x) {
        float ap = -1e30f, an = 1e30f;
        #pragma unroll
        for (int t = 0; t < NT_COL; t++) {
            ap = fmaxf(ap, g_ap[(size_t)r * NT_COL + t]);
            an = fminf(an, g_an[(size_t)r * NT_COL + t]);
        }
        s += fmaxf(ap - an + MARGIN_F, 0.f);
    }
    #pragma unroll
    for (int o = 16; o > 0; o >>= 1) s += __shfl_xor_sync(0xffffffffu, s, o);
    __shared__ float sm[8];
    if ((threadIdx.x & 31) == 0) sm[threadIdx.x >> 5] = s;
    __syncthreads();
    if (threadIdx.x == 0) {
        float t = 0.f;
        #pragma unroll
        for (int i = 0; i < 8; i++) t += sm[i];
        out[0] = t / (float)HALF;
    }
}

// ---------------------------------------------------------------------------
extern "C" void kernel_launch(void* const* d_in, const int* in_sizes, int n_in,
                              void* d_out, int out_size) {
    const float* A       = (const float*)d_in[0];   // [4096, 2048] fp32
    const int*   targets = (const int*)d_in[1];     // [4096] int32
    (void)in_sizes; (void)n_in; (void)out_size;
    float* out = (float*)d_out;

    cudaFuncSetAttribute(dist_imma_kernel,
                         cudaFuncAttributeMaxDynamicSharedMemorySize, SMEM_TOTAL);

    quant_sq_kernel<<<N_ROWS, 256>>>(A);
    dim3 grid(NT_COL, NT_ROW);
    dist_imma_kernel<<<grid, 256, SMEM_TOTAL>>>(targets);
    loss_kernel<<<1, 256>>>(out);
}

// round 7
// speedup vs baseline: 7.6500x; 1.0698x over previous
#include <cuda_runtime.h>
#include <cuda_bf16.h>
#include <cstdint>

// ---------------------------------------------------------------------------
// Problem constants
// ---------------------------------------------------------------------------
#define N_ROWS 4096
#define DIM    2048
#define HALF   2048
#define TILE_M 128
#define TILE_N 128
#define KC     128                // int8 elems per K chunk (128 B per row)
#define NKC    (DIM / KC)         // 16 chunks
#define NT_COL (N_ROWS / TILE_N)  // 32 column tiles
#define LT     16                 // left-half tiles per side (2048/128)
#define NTILES_TRI (LT * (LT + 1) / 2)          // 136 upper-tri incl diag
#define NTILES_TOT (NTILES_TRI + LT * LT)       // 136 + 256 = 392
#define MARGIN_F 0.3f
#define SLAB_BYTES ((size_t)N_ROWS * 128)   // bytes per K-chunk slab in g_Aq

// SMEM layout (dynamic)
#define STAGE_BYTES 32768         // A tile 16KB + B tile 16KB
#define STAGES 3
#define OFF_MBAR 98304            // 3 x 8B mbarriers
#define OFF_SQC  98432
#define OFF_TGC  98944
#define OFF_SQR  99456
#define OFF_TGR  99968
#define OFF_SCR  100480           // row quant scales
#define OFF_SCC  100992           // col quant scales
#define OFF_RAP  101504           // 128*4 floats (row partials)
#define OFF_RAN  103552
#define OFF_CAP  105600           // 128*2 floats (col partials, transposed out)
#define OFF_CAN  106624
#define SMEM_TOTAL 107648

// Scratch (__device__ globals; allocation-free rule)
// Layout: [chunk][row][128B], SW128 swizzle pre-applied, so a 128-row tile slab
// is 16KB contiguous and bulk-copies directly into the ldmatrix-ready image.
__device__ __align__(128) int8_t g_Aq[(size_t)N_ROWS * DIM];   // 8 MB
__device__ float g_sq[N_ROWS];
__device__ float g_scale[N_ROWS];
__device__ float g_ap[HALF * NT_COL];
__device__ float g_an[HALF * NT_COL];

// ---------------------------------------------------------------------------
// PTX helpers (sm_80/sm_90 baseline: ldmatrix, mma.sync, cp.async.bulk, mbarrier)
// ---------------------------------------------------------------------------
__device__ __forceinline__ uint32_t smem_u32(const void* p) {
    uint32_t a;
    asm("{ .reg .u64 t; cvta.to.shared.u64 t, %1; cvt.u32.u64 %0, t; }" : "=r"(a) : "l"(p));
    return a;
}
__device__ __forceinline__ void mbar_init(uint32_t a, uint32_t cnt) {
    asm volatile("mbarrier.init.shared.b64 [%0], %1;" :: "r"(a), "r"(cnt) : "memory");
}
__device__ __forceinline__ void mbar_expect_tx(uint32_t a, uint32_t bytes) {
    asm volatile("mbarrier.arrive.expect_tx.shared.b64 _, [%0], %1;"
                 :: "r"(a), "r"(bytes) : "memory");
}
__device__ __forceinline__ void mbar_wait(uint32_t a, uint32_t parity) {
    asm volatile(
        "{\n\t.reg .pred P;\n"
        "W_%=:\n\t"
        "mbarrier.try_wait.parity.shared.b64 P, [%0], %1, 0x989680;\n\t"
        "@P bra.uni D_%=;\n\t"
        "bra.uni W_%=;\n"
        "D_%=:\n\t}"
        :: "r"(a), "r"(parity) : "memory");
}
__device__ __forceinline__ void bulk_g2s(uint32_t sdst, const void* gsrc,
                                         uint32_t bytes, uint32_t mbar) {
    asm volatile(
        "cp.async.bulk.shared::cta.global.mbarrier::complete_tx::bytes [%0], [%1], %2, [%3];"
        :: "r"(sdst), "l"(gsrc), "r"(bytes), "r"(mbar) : "memory");
}
__device__ __forceinline__ void ldmatrix_x4(uint32_t* r, uint32_t addr) {
    asm volatile("ldmatrix.sync.aligned.m8n8.x4.shared.b16 {%0,%1,%2,%3}, [%4];"
                 : "=r"(r[0]), "=r"(r[1]), "=r"(r[2]), "=r"(r[3]) : "r"(addr));
}
// int8 MMA: byte-level fragment layout identical to bf16 m16n8k16 (b16 == 2 x s8)
__device__ __forceinline__ void mma_s8(int* c, const uint32_t* a, uint32_t b0, uint32_t b1) {
    asm volatile(
        "mma.sync.aligned.m16n8k32.row.col.s32.s8.s8.s32 "
        "{%0,%1,%2,%3}, {%4,%5,%6,%7}, {%8,%9}, {%0,%1,%2,%3};"
        : "+r"(c[0]), "+r"(c[1]), "+r"(c[2]), "+r"(c[3])
        : "r"(a[0]), "r"(a[1]), "r"(a[2]), "r"(a[3]), "r"(b0), "r"(b1));
}
// SW128 swizzle on a 128-byte row: 16B chunk index XOR (row & 7)
__device__ __forceinline__ uint32_t sw_off(uint32_t r, uint32_t c8) {
    return r * 128u + ((c8 ^ (r & 7u)) << 4);
}

// ---------------------------------------------------------------------------
// Kernel 1: per-row absmax quantize fp32 -> int8 (pre-swizzled chunk-blocked
// layout) + row sum-of-squares (fp32). One block (256 thr) per row.
// ---------------------------------------------------------------------------
__global__ void quant_sq_kernel(const float* __restrict__ A) {
    const int row = blockIdx.x;
    const float4* a4 = reinterpret_cast<const float4*>(A + (size_t)row * DIM);
    float4 v0 = a4[threadIdx.x];
    float4 v1 = a4[threadIdx.x + 256];

    float s = v0.x * v0.x + v0.y * v0.y + v0.z * v0.z + v0.w * v0.w
            + v1.x * v1.x + v1.y * v1.y + v1.z * v1.z + v1.w * v1.w;
    float m = fmaxf(fmaxf(fmaxf(fabsf(v0.x), fabsf(v0.y)), fmaxf(fabsf(v0.z), fabsf(v0.w))),
                    fmaxf(fmaxf(fabsf(v1.x), fabsf(v1.y)), fmaxf(fabsf(v1.z), fabsf(v1.w))));
    #pragma unroll
    for (int o = 16; o > 0; o >>= 1) {
        s += __shfl_xor_sync(0xffffffffu, s, o);
        m = fmaxf(m, __shfl_xor_sync(0xffffffffu, m, o));
    }
    __shared__ float sm_s[8], sm_m[8];
    if ((threadIdx.x & 31) == 0) { sm_s[threadIdx.x >> 5] = s; sm_m[threadIdx.x >> 5] = m; }
    __syncthreads();
    float ts = 0.f, tm = 0.f;
    #pragma unroll
    for (int i = 0; i < 8; i++) { ts += sm_s[i]; tm = fmaxf(tm, sm_m[i]); }
    if (threadIdx.x == 0) {
        g_sq[row] = ts;
        g_scale[row] = fmaxf(tm, 1e-30f) / 127.0f;
    }
    const float inv = 127.0f / fmaxf(tm, 1e-30f);

    uint32_t* q32 = reinterpret_cast<uint32_t*>(g_Aq);
    auto pack = [inv](float4 v) -> uint32_t {
        int q0 = __float2int_rn(v.x * inv), q1 = __float2int_rn(v.y * inv);
        int q2 = __float2int_rn(v.z * inv), q3 = __float2int_rn(v.w * inv);
        return (uint32_t)(uint8_t)(int8_t)q0 | ((uint32_t)(uint8_t)(int8_t)q1 << 8) |
               ((uint32_t)(uint8_t)(int8_t)q2 << 16) | ((uint32_t)(uint8_t)(int8_t)q3 << 24);
    };
    // j32 = 4-byte column index in [0, 512). chunk = j32>>5; c8 = (j32>>2)&7.
    auto qidx = [row](int j32) -> size_t {
        const int c  = j32 >> 5;
        const int c8 = (j32 >> 2) & 7;
        const int w  = j32 & 3;
        const size_t byteoff = (size_t)c * SLAB_BYTES + (size_t)row * 128 +
                               (size_t)(((uint32_t)c8 ^ ((uint32_t)row & 7u)) << 4) + w * 4;
        return byteoff >> 2;
    };
    q32[qidx(threadIdx.x)]       = pack(v0);
    q32[qidx(threadIdx.x + 256)] = pack(v1);
}

// ---------------------------------------------------------------------------
// Kernel 2: int8 warp-MMA Gram tile (128x128) + fused dist/mask/max-min.
// Symmetric schedule: 136 upper-tri left-half tiles (off-diagonal ones also
// emit transposed column partials) + 256 right-half tiles. 392 blocks total.
// 256 threads = 8 warps in 2x4 (each warp 64x32).
// ---------------------------------------------------------------------------
__global__ __launch_bounds__(256, 2)
void dist_imma_kernel(const int* __restrict__ targets) {
    extern __shared__ __align__(128) char smem[];
    const uint32_t sb = smem_u32(smem);
    const int tid = threadIdx.x;
    const int lane = tid & 31;
    const int w = tid >> 5;

    // ---- tile decode ----
    int tileM, tileN;
    bool doTrans;
    {
        int idx = blockIdx.x;
        if (idx < NTILES_TRI) {
            int a = 0, t = idx;
            #pragma unroll 1
            while (t >= LT - a) { t -= LT - a; ++a; }
            tileM = a; tileN = a + t;
            doTrans = (tileN != tileM);
        } else {
            int li = idx - NTILES_TRI;
            tileM = li >> 4;
            tileN = LT + (li & 15);
            doTrans = false;
        }
    }
    const int rowBase = tileM * TILE_M;
    const int colBase = tileN * TILE_N;

    float* s_sqc = reinterpret_cast<float*>(smem + OFF_SQC);
    int*   s_tgc = reinterpret_cast<int*>(smem + OFF_TGC);
    float* s_sqr = reinterpret_cast<float*>(smem + OFF_SQR);
    int*   s_tgr = reinterpret_cast<int*>(smem + OFF_TGR);
    float* s_scr = reinterpret_cast<float*>(smem + OFF_SCR);
    float* s_scc = reinterpret_cast<float*>(smem + OFF_SCC);
    float* s_rap = reinterpret_cast<float*>(smem + OFF_RAP);
    float* s_ran = reinterpret_cast<float*>(smem + OFF_RAN);
    float* s_cap = reinterpret_cast<float*>(smem + OFF_CAP);
    float* s_can = reinterpret_cast<float*>(smem + OFF_CAN);

    if (tid == 0) {
        #pragma unroll
        for (int s = 0; s < STAGES; ++s) mbar_init(sb + OFF_MBAR + s * 8, 1);
    }
    if (tid < TILE_N) {
        s_sqc[tid] = g_sq[colBase + tid];
        s_tgc[tid] = targets[colBase + tid];
        s_scc[tid] = g_scale[colBase + tid];
        s_sqr[tid] = g_sq[rowBase + tid];
        s_tgr[tid] = targets[rowBase + tid];
        s_scr[tid] = g_scale[rowBase + tid];
    }
    __syncthreads();

    auto issue_chunk = [&](int s, int chunk) {
        const uint32_t mbar = sb + OFF_MBAR + s * 8;
        const uint32_t st = sb + (uint32_t)s * STAGE_BYTES;
        mbar_expect_tx(mbar, STAGE_BYTES);
        bulk_g2s(st, g_Aq + (size_t)chunk * SLAB_BYTES + (size_t)rowBase * 128,
                 16384u, mbar);
        bulk_g2s(st + 16384u, g_Aq + (size_t)chunk * SLAB_BYTES + (size_t)colBase * 128,
                 16384u, mbar);
    };
    if (tid == 0) {
        issue_chunk(0, 0);
        issue_chunk(1, 1);
        issue_chunk(2, 2);
    }

    int acc[4][4][4];
    #pragma unroll
    for (int i = 0; i < 4; i++)
        #pragma unroll
        for (int j = 0; j < 4; j++)
            #pragma unroll
            for (int e = 0; e < 4; e++) acc[i][j][e] = 0;

    const int mBase = (w >> 2) * 64;
    const int nBase = (w & 3) * 32;
    uint32_t ph0 = 0, ph1 = 0, ph2 = 0;

    for (int c = 0; c < NKC; ++c) {
        const int s = c % STAGES;
        uint32_t& ph = (s == 0) ? ph0 : (s == 1) ? ph1 : ph2;
        mbar_wait(sb + OFF_MBAR + s * 8, ph & 1);
        ph++;

        const uint32_t stA = sb + (uint32_t)s * STAGE_BYTES;
        const uint32_t stB = stA + 16384u;
        #pragma unroll
        for (int ks = 0; ks < 4; ++ks) {           // 4 x k32(int8) per 128-chunk
            uint32_t a[4][4];
            #pragma unroll
            for (int mi = 0; mi < 4; ++mi) {
                const uint32_t r = mBase + mi * 16 + (lane & 15);
                const uint32_t c8 = ks * 2 + (lane >> 4);
                ldmatrix_x4(a[mi], stA + sw_off(r, c8));
            }
            uint32_t b[2][4];
            #pragma unroll
            for (int nb = 0; nb < 2; ++nb) {
                const uint32_t r = nBase + nb * 16 + ((lane >> 4) << 3) + (lane & 7);
                const uint32_t c8 = ks * 2 + ((lane >> 3) & 1);
                ldmatrix_x4(b[nb], stB + sw_off(r, c8));
            }
            #pragma unroll
            for (int mi = 0; mi < 4; ++mi)
                #pragma unroll
                for (int nj = 0; nj < 4; ++nj)
                    mma_s8(acc[mi][nj], a[mi], b[nj >> 1][(nj & 1) * 2],
                           b[nj >> 1][(nj & 1) * 2 + 1]);
        }
        __syncthreads();               // all warps done with stage s
        if (tid == 0 && c + STAGES < NKC) issue_chunk(s, c + STAGES);
    }

    // ---- Epilogue ----
    // Fragment layout (m16n8): thread holds rows (qrow, qrow+8), cols (qcol*2, +1).
    const int qrow = lane >> 2;
    const int qcol = lane & 3;

    // Pass 0: convert int accumulators to distances in place (bitcast storage).
    float* dv = reinterpret_cast<float*>(&acc[0][0][0]);
    #pragma unroll
    for (int mi = 0; mi < 4; ++mi) {
        #pragma unroll
        for (int h = 0; h < 2; ++h) {
            const int rl = mBase + mi * 16 + qrow + h * 8;
            const float sqr = s_sqr[rl];
            const float sr2 = 2.0f * s_scr[rl];
            #pragma unroll
            for (int nj = 0; nj < 4; ++nj) {
                #pragma unroll
                for (int cc = 0; cc < 2; ++cc) {
                    const int cl = nBase + nj * 8 + qcol * 2 + cc;
                    const int e = h * 2 + cc;
                    const float dot = sr2 * s_scc[cl] * (float)acc[mi][nj][e];
                    const float d2 = sqr + s_sqc[cl] - dot;
                    dv[(mi * 4 + nj) * 4 + e] = sqrtf(fmaxf(d2, 1e-12f));
                }
            }
        }
    }

    // Pass 1: row-side masked max/min.
    #pragma unroll
    for (int mi = 0; mi < 4; ++mi) {
        #pragma unroll
        for (int h = 0; h < 2; ++h) {
            const int rl = mBase + mi * 16 + qrow + h * 8;
            const int tgr = s_tgr[rl];
            float ap = -1e30f, an = 1e30f;
            #pragma unroll
            for (int nj = 0; nj < 4; ++nj) {
                #pragma unroll
                for (int cc = 0; cc < 2; ++cc) {
                    const int cl = nBase + nj * 8 + qcol * 2 + cc;
                    const float d = dv[(mi * 4 + nj) * 4 + h * 2 + cc];
                    if (s_tgc[cl] == tgr) ap = fmaxf(ap, d);
                    else                  an = fminf(an, d);
                }
            }
            ap = fmaxf(ap, __shfl_xor_sync(0xffffffffu, ap, 1));
            ap = fmaxf(ap, __shfl_xor_sync(0xffffffffu, ap, 2));
            an = fminf(an, __shfl_xor_sync(0xffffffffu, an, 1));
            an = fminf(an, __shfl_xor_sync(0xffffffffu, an, 2));
            if (qcol == 0) {
                s_rap[rl * 4 + (w & 3)] = ap;
                s_ran[rl * 4 + (w & 3)] = an;
            }
        }
    }

    // Pass 2 (off-diagonal left-half tiles): column-side masked max/min —
    // this is the transposed tile's row reduction (mask symmetric, d symmetric).
    if (doTrans) {
        #pragma unroll
        for (int nj = 0; nj < 4; ++nj) {
            #pragma unroll
            for (int cc = 0; cc < 2; ++cc) {
                const int cl = nBase + nj * 8 + qcol * 2 + cc;
                const int tgc = s_tgc[cl];
                float ap = -1e30f, an = 1e30f;
                #pragma unroll
                for (int mi = 0; mi < 4; ++mi) {
                    #pragma unroll
                    for (int h = 0; h < 2; ++h) {
                        const int rl = mBase + mi * 16 + qrow + h * 8;
                        const float d = dv[(mi * 4 + nj) * 4 + h * 2 + cc];
                        if (s_tgr[rl] == tgc) ap = fmaxf(ap, d);
                        else                  an = fminf(an, d);
                    }
                }
                ap = fmaxf(ap, __shfl_xor_sync(0xffffffffu, ap, 4));
                ap = fmaxf(ap, __shfl_xor_sync(0xffffffffu, ap, 8));
                ap = fmaxf(ap, __shfl_xor_sync(0xffffffffu, ap, 16));
                an = fminf(an, __shfl_xor_sync(0xffffffffu, an, 4));
                an = fminf(an, __shfl_xor_sync(0xffffffffu, an, 8));
                an = fminf(an, __shfl_xor_sync(0xffffffffu, an, 16));
                if (qrow == 0) {
                    s_cap[cl * 2 + (w >> 2)] = ap;
                    s_can[cl * 2 + (w >> 2)] = an;
                }
            }
        }
    }
    __syncthreads();

    if (tid < TILE_M) {
        float ap = -1e30f, an = 1e30f;
        #pragma unroll
        for (int t = 0; t < 4; ++t) {
            ap = fmaxf(ap, s_rap[tid * 4 + t]);
            an = fminf(an, s_ran[tid * 4 + t]);
        }
        g_ap[(size_t)(rowBase + tid) * NT_COL + tileN] = ap;
        g_an[(size_t)(rowBase + tid) * NT_COL + tileN] = an;
        if (doTrans) {
            const float cap = fmaxf(s_cap[tid * 2], s_cap[tid * 2 + 1]);
            const float can = fminf(s_can[tid * 2], s_can[tid * 2 + 1]);
            g_ap[(size_t)(colBase + tid) * NT_COL + tileM] = cap;
            g_an[(size_t)(colBase + tid) * NT_COL + tileM] = can;
        }
    }
}

// ---------------------------------------------------------------------------
// Kernel 3: deterministic final reduction -> scalar loss.
// ---------------------------------------------------------------------------
__global__ void loss_kernel(float* __restrict__ out) {
    float s = 0.f;
    for (int r = threadIdx.x; r < HALF; r += blockDim.x) {
        float ap = -1e30f, an = 1e30f;
        #pragma unroll
        for (int t = 0; t < NT_COL; t++) {
            ap = fmaxf(ap, g_ap[(size_t)r * NT_COL + t]);
            an = fminf(an, g_an[(size_t)r * NT_COL + t]);
        }
        s += fmaxf(ap - an + MARGIN_F, 0.f);
    }
    #pragma unroll
    for (int o = 16; o > 0; o >>= 1) s += __shfl_xor_sync(0xffffffffu, s, o);
    __shared__ float sm[8];
    if ((threadIdx.x & 31) == 0) sm[threadIdx.x >> 5] = s;
    __syncthreads();
    if (threadIdx.x == 0) {
        float t = 0.f;
        #pragma unroll
        for (int i = 0; i < 8; i++) t += sm[i];
        out[0] = t / (float)HALF;
    }
}

// ---------------------------------------------------------------------------
extern "C" void kernel_launch(void* const* d_in, const int* in_sizes, int n_in,
                              void* d_out, int out_size) {
    const float* A       = (const float*)d_in[0];   // [4096, 2048] fp32
    const int*   targets = (const int*)d_in[1];     // [4096] int32
    (void)in_sizes; (void)n_in; (void)out_size;
    float* out = (float*)d_out;

    cudaFuncSetAttribute(dist_imma_kernel,
                         cudaFuncAttributeMaxDynamicSharedMemorySize, SMEM_TOTAL);

    quant_sq_kernel<<<N_ROWS, 256>>>(A);
    dist_imma_kernel<<<NTILES_TOT, 256, SMEM_TOTAL>>>(targets);
    loss_kernel<<<1, 256>>>(out);
}